// round 5
// baseline (speedup 1.0000x reference)
#include <cuda_runtime.h>
#include <cuda_bf16.h>
#include <cuda_fp16.h>
#include <math.h>

#define NNODES 50000
#define NEDGES 800000
#define ETOT   (NEDGES + NNODES)
#define SCAN_T 1024

// ---------------- device scratch ----------------
__device__ __half g_y2[NNODES * 256];    // folded features fp16, scatter-packed:
                                         // y2[n][16*sub + 4*h + i] = y[n][h][4*sub+i]
__device__ float  g_asrc[NNODES * 4];
__device__ float  g_adst[NNODES * 4];
__device__ float  g_denom[NNODES * 4];
__device__ float  g_ex[ETOT * 4];
__device__ int2   g_sd[ETOT];
__device__ int    g_cnt[NNODES];         // edges per dst
__device__ int    g_base[NNODES];        // exclusive prefix (group start)
__device__ int    g_off[NNODES];         // placement cursor
__device__ int    g_msrc[ETOT];          // dst-sorted: src index
__device__ float4 g_mcoef[ETOT];         // dst-sorted: per-head coef
__device__ int    g_is64;
__device__ __half g_wfh[256 * 64];       // folded weights fp16, transposed [n][k]
__device__ float  g_ws[64 * 4];
__device__ float  g_wd[64 * 4];
__device__ float  g_b2[64];              // dense_b + bias @ dense_w

// ---------------- prep: folds + b2 + dtype detect ----------------
__global__ void __launch_bounds__(64) k_prep(const float* __restrict__ W,
                                             const float* __restrict__ dw,
                                             const float* __restrict__ asr,
                                             const float* __restrict__ adt,
                                             const float* __restrict__ bias,
                                             const float* __restrict__ db,
                                             const int* __restrict__ g32) {
    int b = blockIdx.x;
    int k = threadIdx.x;
    if (b < 256) {
        int j = b, h = j >> 6, d = j & 63;
        __shared__ float dcol[64];
        dcol[k] = dw[(h * 64 + k) * 64 + d];
        __syncthreads();
        const float4* wr = (const float4*)&W[k * 256 + h * 64];
        float acc = 0.f;
        #pragma unroll
        for (int q = 0; q < 16; q++) {
            float4 w4 = wr[q];
            acc = fmaf(w4.x, dcol[4 * q + 0], acc);
            acc = fmaf(w4.y, dcol[4 * q + 1], acc);
            acc = fmaf(w4.z, dcol[4 * q + 2], acc);
            acc = fmaf(w4.w, dcol[4 * q + 3], acc);
        }
        g_wfh[j * 64 + k] = __float2half_rn(acc);
    } else if (b < 264) {
        int bb = b - 256;
        int sel = bb >> 2, h = bb & 3;
        __shared__ float av[64];
        av[k] = sel ? adt[h * 64 + k] : asr[h * 64 + k];
        __syncthreads();
        const float4* wr = (const float4*)&W[k * 256 + h * 64];
        float acc = 0.f;
        #pragma unroll
        for (int q = 0; q < 16; q++) {
            float4 w4 = wr[q];
            acc = fmaf(w4.x, av[4 * q + 0], acc);
            acc = fmaf(w4.y, av[4 * q + 1], acc);
            acc = fmaf(w4.z, av[4 * q + 2], acc);
            acc = fmaf(w4.w, av[4 * q + 3], acc);
        }
        if (sel) g_wd[k * 4 + h] = acc; else g_ws[k * 4 + h] = acc;
    } else if (b == 264) {
        float acc = db[k];
        #pragma unroll 8
        for (int c = 0; c < 256; c++) acc = fmaf(bias[c], dw[c * 64 + k], acc);
        g_b2[k] = acc;
    } else {
        __shared__ int any_nonzero;
        if (k == 0) any_nonzero = 0;
        __syncthreads();
        int nz = 0;
        #pragma unroll
        for (int r = 0; r < 4; r++) nz |= g32[2 * (k + 64 * r) + 1];
        if (nz != 0) any_nonzero = 1;
        __syncthreads();
        if (k == 0) g_is64 = (any_nonzero == 0) ? 1 : 0;
    }
}

// ---------------- phase 1 (fused, HMMA): block = 64 nodes ----------------
__global__ void __launch_bounds__(256) k_phase1(const float* __restrict__ emb, int N) {
    __shared__ float  sf[64 * 68];     // fp32 emb tile [row][k]
    __shared__ __half ah[64 * 72];     // fp16 emb tile [row][k]
    __shared__ float  s_w[64 * 8];
    int t = threadIdx.x;
    int base = blockIdx.x * 64;

    for (int i = t; i < 512; i += 256) {
        int k = i >> 3, c = i & 7;
        s_w[i] = (c < 4) ? g_ws[k * 4 + c] : g_wd[k * 4 + (c - 4)];
    }
    #pragma unroll
    for (int j = 0; j < 16; j++) {
        int g = j * 256 + t;
        int ro = g >> 6, k = g & 63;
        int row = base + ro;
        float v = (row < N) ? emb[row * 64 + k] : 0.f;
        sf[ro * 68 + k] = v;
        ah[ro * 72 + k] = __float2half_rn(v);
    }
    __syncthreads();

    // ---- zero denom + edge histogram counters ----
    {
        int ro = t >> 2, q = t & 3;
        int node = base + ro;
        if (node < N) {
            g_denom[node * 4 + q] = 0.f;
            if (q == 0) g_cnt[node] = 0;
        }
    }

    // ---- proj via mma.sync m16n8k16 ----
    {
        int w = t >> 5, lane = t & 31;
        int gid = lane >> 2, tig = lane & 3;

        unsigned bfr[4][4][2];
        #pragma unroll
        for (int tn = 0; tn < 4; tn++) {
            int n = 32 * w + 8 * tn + gid;
            #pragma unroll
            for (int ks = 0; ks < 4; ks++) {
                bfr[tn][ks][0] = *(const unsigned*)&g_wfh[n * 64 + 16 * ks + 2 * tig];
                bfr[tn][ks][1] = *(const unsigned*)&g_wfh[n * 64 + 16 * ks + 2 * tig + 8];
            }
        }

        float acc[4][4][4];
        #pragma unroll
        for (int mg = 0; mg < 4; mg++)
            #pragma unroll
            for (int tn = 0; tn < 4; tn++)
                #pragma unroll
                for (int q = 0; q < 4; q++) acc[mg][tn][q] = 0.f;

        #pragma unroll
        for (int mg = 0; mg < 4; mg++) {
            int r0 = 16 * mg + gid;
            #pragma unroll
            for (int ks = 0; ks < 4; ks++) {
                unsigned a0 = *(const unsigned*)&ah[r0 * 72 + 16 * ks + 2 * tig];
                unsigned a1 = *(const unsigned*)&ah[(r0 + 8) * 72 + 16 * ks + 2 * tig];
                unsigned a2 = *(const unsigned*)&ah[r0 * 72 + 16 * ks + 2 * tig + 8];
                unsigned a3 = *(const unsigned*)&ah[(r0 + 8) * 72 + 16 * ks + 2 * tig + 8];
                #pragma unroll
                for (int tn = 0; tn < 4; tn++) {
                    asm("mma.sync.aligned.m16n8k16.row.col.f32.f16.f16.f32 "
                        "{%0,%1,%2,%3}, {%4,%5,%6,%7}, {%8,%9}, {%0,%1,%2,%3};"
                        : "+f"(acc[mg][tn][0]), "+f"(acc[mg][tn][1]),
                          "+f"(acc[mg][tn][2]), "+f"(acc[mg][tn][3])
                        : "r"(a0), "r"(a1), "r"(a2), "r"(a3),
                          "r"(bfr[tn][ks][0]), "r"(bfr[tn][ks][1]));
                }
            }
        }

        #pragma unroll
        for (int mg = 0; mg < 4; mg++) {
            #pragma unroll
            for (int tn = 0; tn < 4; tn++) {
                int j = 32 * w + 8 * tn + 2 * tig;
                int h = j >> 6, d = j & 63;
                int idx = 16 * (d >> 2) + 4 * h + (d & 3);
                int r = base + 16 * mg + gid;
                if (r < N) {
                    __half2 v = __floats2half2_rn(acc[mg][tn][0], acc[mg][tn][1]);
                    *(__half2*)&g_y2[(size_t)r * 256 + idx] = v;
                }
                if (r + 8 < N) {
                    __half2 v = __floats2half2_rn(acc[mg][tn][2], acc[mg][tn][3]);
                    *(__half2*)&g_y2[(size_t)(r + 8) * 256 + idx] = v;
                }
            }
        }
    }

    // ---- att logits (fp32) ----
    {
        int i = t >> 2, hh = t & 3;
        float as = 0.f, ad = 0.f;
        #pragma unroll 8
        for (int k = 0; k < 64; k++) {
            float e = sf[i * 68 + k];
            as = fmaf(e, s_w[k * 8 + hh], as);
            ad = fmaf(e, s_w[k * 8 + 4 + hh], ad);
        }
        int node = base + i;
        if (node < N) {
            g_asrc[node * 4 + hh] = as;
            g_adst[node * 4 + hh] = ad;
        }
    }
}

// ---------------- edge pass 1: ex, denom, dst histogram ----------------
__global__ void k_edge(const void* __restrict__ graph, int E, int ET) {
    int e = blockIdx.x * blockDim.x + threadIdx.x;
    if (e >= ET) return;
    int s, d;
    if (e < E) {
        if (g_is64) {
            const long long* g = (const long long*)graph;
            s = (int)g[e]; d = (int)g[E + e];
        } else {
            const int* g = (const int*)graph;
            s = g[e]; d = g[E + e];
        }
    } else {
        s = d = e - E;   // self loop
    }
    g_sd[e] = make_int2(s, d);

    float4 as4 = *(const float4*)&g_asrc[s * 4];
    float4 ad4 = *(const float4*)&g_adst[d * 4];
    float a0 = as4.x + ad4.x, a1 = as4.y + ad4.y, a2 = as4.z + ad4.z, a3 = as4.w + ad4.w;
    a0 = (a0 > 0.f) ? a0 : 0.2f * a0;
    a1 = (a1 > 0.f) ? a1 : 0.2f * a1;
    a2 = (a2 > 0.f) ? a2 : 0.2f * a2;
    a3 = (a3 > 0.f) ? a3 : 0.2f * a3;
    float4 ex4 = make_float4(__expf(a0), __expf(a1), __expf(a2), __expf(a3));
    *(float4*)&g_ex[e * 4] = ex4;

    float* dp = &g_denom[d * 4];
    asm volatile("red.global.v4.f32.add [%0], {%1, %2, %3, %4};"
                 :: "l"(dp), "f"(ex4.x), "f"(ex4.y), "f"(ex4.z), "f"(ex4.w)
                 : "memory");
    asm volatile("red.global.add.s32 [%0], 1;" :: "l"(&g_cnt[d]) : "memory");
}

// ---------------- exclusive scan over g_cnt (one block) ----------------
__global__ void __launch_bounds__(SCAN_T) k_scan(int N) {
    __shared__ int s[SCAN_T];
    int t = threadIdx.x;
    int C = (N + SCAN_T - 1) / SCAN_T;
    int lo = t * C, hi = (lo + C < N) ? lo + C : N;
    int sum = 0;
    for (int i = lo; i < hi; i++) sum += g_cnt[i];
    s[t] = sum;
    __syncthreads();
    for (int o = 1; o < SCAN_T; o <<= 1) {
        int u = (t >= o) ? s[t - o] : 0;
        __syncthreads();
        s[t] += u;
        __syncthreads();
    }
    int run = s[t] - sum;   // exclusive
    for (int i = lo; i < hi; i++) {
        int c = g_cnt[i];
        g_base[i] = run;
        g_off[i]  = run;
        run += c;
    }
}

// ---------------- place edges into dst-sorted order, with fp32 coef ----------
__global__ void k_place(int ET) {
    int e = blockIdx.x * blockDim.x + threadIdx.x;
    if (e >= ET) return;
    int2 sd = g_sd[e];
    float4 ex4 = *(const float4*)&g_ex[e * 4];
    float4 dn  = *(const float4*)&g_denom[sd.y * 4];
    float4 c;
    c.x = __fdividef(ex4.x, dn.x + 1e-16f);
    c.y = __fdividef(ex4.y, dn.y + 1e-16f);
    c.z = __fdividef(ex4.z, dn.z + 1e-16f);
    c.w = __fdividef(ex4.w, dn.w + 1e-16f);
    int pos = atomicAdd(&g_off[sd.y], 1);
    g_msrc[pos] = sd.x;
    g_mcoef[pos] = c;
}

// ---------------- scatter2: 16 lanes per dst node, register accumulate ------
__global__ void __launch_bounds__(256) k_scatter2(float* __restrict__ out, int N) {
    int tid = blockIdx.x * blockDim.x + threadIdx.x;
    int g = tid >> 4, sub = tid & 15;
    if (g >= N) return;
    int base = g_base[g];
    int n = g_cnt[g];

    float4 acc = make_float4(0.f, 0.f, 0.f, 0.f);

    int src_n = 0; float4 c_n = make_float4(0.f, 0.f, 0.f, 0.f);
    if (n > 0) { src_n = __ldg(&g_msrc[base]); c_n = __ldg(&g_mcoef[base]); }

    for (int i = 0; i < n; i++) {
        int src = src_n; float4 c = c_n;
        if (i + 1 < n) {
            src_n = __ldg(&g_msrc[base + i + 1]);
            c_n   = __ldg(&g_mcoef[base + i + 1]);
        }
        const uint4* yp = (const uint4*)&g_y2[(size_t)src * 256];
        uint4 ua = __ldg(&yp[2 * sub]);
        uint4 ub = __ldg(&yp[2 * sub + 1]);

        float2 h0a = __half22float2(*(__half2*)&ua.x);
        float2 h0b = __half22float2(*(__half2*)&ua.y);
        float2 h1a = __half22float2(*(__half2*)&ua.z);
        float2 h1b = __half22float2(*(__half2*)&ua.w);
        float2 h2a = __half22float2(*(__half2*)&ub.x);
        float2 h2b = __half22float2(*(__half2*)&ub.y);
        float2 h3a = __half22float2(*(__half2*)&ub.z);
        float2 h3b = __half22float2(*(__half2*)&ub.w);

        acc.x += fmaf(c.w, h3a.x, fmaf(c.z, h2a.x, fmaf(c.y, h1a.x, c.x * h0a.x)));
        acc.y += fmaf(c.w, h3a.y, fmaf(c.z, h2a.y, fmaf(c.y, h1a.y, c.x * h0a.y)));
        acc.z += fmaf(c.w, h3b.x, fmaf(c.z, h2b.x, fmaf(c.y, h1b.x, c.x * h0b.x)));
        acc.w += fmaf(c.w, h3b.y, fmaf(c.z, h2b.y, fmaf(c.y, h1b.y, c.x * h0b.y)));
    }

    float4 b4 = *(const float4*)&g_b2[4 * sub];
    acc.x += b4.x; acc.y += b4.y; acc.z += b4.z; acc.w += b4.w;
    *(float4*)&out[(size_t)g * 64 + 4 * sub] = acc;
}

// ---------------- launch ----------------
extern "C" void kernel_launch(void* const* d_in, const int* in_sizes, int n_in,
                              void* d_out, int out_size) {
    const float* emb   = (const float*)d_in[0];
    const void*  graph = d_in[1];
    const float* W     = (const float*)d_in[2];
    const float* asr   = (const float*)d_in[3];
    const float* adt   = (const float*)d_in[4];
    const float* bias  = (const float*)d_in[5];
    const float* dw    = (const float*)d_in[6];
    const float* db    = (const float*)d_in[7];
    float* out = (float*)d_out;

    int N  = in_sizes[0] / 64;
    int E  = in_sizes[1] / 2;
    int ET = E + N;

    k_prep<<<266, 64>>>(W, dw, asr, adt, bias, db, (const int*)graph);
    k_phase1<<<(N + 63) / 64, 256>>>(emb, N);
    k_edge<<<(ET + 255) / 256, 256>>>(graph, E, ET);
    k_scan<<<1, SCAN_T>>>(N);
    k_place<<<(ET + 255) / 256, 256>>>(ET);
    k_scatter2<<<((size_t)N * 16 + 255) / 256, 256>>>(out, N);
}

// round 6
// speedup vs baseline: 1.1538x; 1.1538x over previous
#include <cuda_runtime.h>
#include <cuda_bf16.h>
#include <cuda_fp16.h>
#include <math.h>

#define NNODES 50000
#define NEDGES 800000
#define ETOT   (NEDGES + NNODES)

// ---------------- device scratch ----------------
__device__ __half g_y2[NNODES * 256];    // folded features fp16, scatter-packed:
                                         // y2[n][16*sub + 4*h + i] = y[n][h][4*sub+i]
__device__ float  g_asrc[NNODES * 4];
__device__ float  g_adst[NNODES * 4];
__device__ float  g_denom[NNODES * 4];
__device__ float  g_ex[ETOT * 4];
__device__ int2   g_sd[ETOT];
__device__ int    g_cnt[NNODES];         // edges per dst
__device__ int    g_base[NNODES];        // group start in sorted buffer
__device__ int    g_off[NNODES];         // placement cursor
__device__ uint4  g_meta[ETOT];          // dst-sorted: {src, half2 c01, half2 c23, 0}
__device__ int    g_total;               // block-base cursor for scan
__device__ int    g_is64;
__device__ __half g_wfh[256 * 64];       // folded weights fp16, transposed [n][k]
__device__ float  g_ws[64 * 4];
__device__ float  g_wd[64 * 4];
__device__ float  g_b2[64];              // dense_b + bias @ dense_w

// ---------------- prep: folds + b2 + dtype detect ----------------
__global__ void __launch_bounds__(64) k_prep(const float* __restrict__ W,
                                             const float* __restrict__ dw,
                                             const float* __restrict__ asr,
                                             const float* __restrict__ adt,
                                             const float* __restrict__ bias,
                                             const float* __restrict__ db,
                                             const int* __restrict__ g32) {
    int b = blockIdx.x;
    int k = threadIdx.x;
    if (b < 256) {
        int j = b, h = j >> 6, d = j & 63;
        __shared__ float dcol[64];
        dcol[k] = dw[(h * 64 + k) * 64 + d];
        __syncthreads();
        const float4* wr = (const float4*)&W[k * 256 + h * 64];
        float acc = 0.f;
        #pragma unroll
        for (int q = 0; q < 16; q++) {
            float4 w4 = wr[q];
            acc = fmaf(w4.x, dcol[4 * q + 0], acc);
            acc = fmaf(w4.y, dcol[4 * q + 1], acc);
            acc = fmaf(w4.z, dcol[4 * q + 2], acc);
            acc = fmaf(w4.w, dcol[4 * q + 3], acc);
        }
        g_wfh[j * 64 + k] = __float2half_rn(acc);
    } else if (b < 264) {
        int bb = b - 256;
        int sel = bb >> 2, h = bb & 3;
        __shared__ float av[64];
        av[k] = sel ? adt[h * 64 + k] : asr[h * 64 + k];
        __syncthreads();
        const float4* wr = (const float4*)&W[k * 256 + h * 64];
        float acc = 0.f;
        #pragma unroll
        for (int q = 0; q < 16; q++) {
            float4 w4 = wr[q];
            acc = fmaf(w4.x, av[4 * q + 0], acc);
            acc = fmaf(w4.y, av[4 * q + 1], acc);
            acc = fmaf(w4.z, av[4 * q + 2], acc);
            acc = fmaf(w4.w, av[4 * q + 3], acc);
        }
        if (sel) g_wd[k * 4 + h] = acc; else g_ws[k * 4 + h] = acc;
    } else if (b == 264) {
        if (k == 0) g_total = 0;
        float acc = db[k];
        #pragma unroll 8
        for (int c = 0; c < 256; c++) acc = fmaf(bias[c], dw[c * 64 + k], acc);
        g_b2[k] = acc;
    } else {
        __shared__ int any_nonzero;
        if (k == 0) any_nonzero = 0;
        __syncthreads();
        int nz = 0;
        #pragma unroll
        for (int r = 0; r < 4; r++) nz |= g32[2 * (k + 64 * r) + 1];
        if (nz != 0) any_nonzero = 1;
        __syncthreads();
        if (k == 0) g_is64 = (any_nonzero == 0) ? 1 : 0;
    }
}

// ---------------- phase 1 (fused, HMMA): block = 64 nodes ----------------
__global__ void __launch_bounds__(256) k_phase1(const float* __restrict__ emb, int N) {
    __shared__ float  sf[64 * 68];     // fp32 emb tile [row][k]
    __shared__ __half ah[64 * 72];     // fp16 emb tile [row][k]
    __shared__ float  s_w[64 * 8];
    int t = threadIdx.x;
    int base = blockIdx.x * 64;

    for (int i = t; i < 512; i += 256) {
        int k = i >> 3, c = i & 7;
        s_w[i] = (c < 4) ? g_ws[k * 4 + c] : g_wd[k * 4 + (c - 4)];
    }
    #pragma unroll
    for (int j = 0; j < 16; j++) {
        int g = j * 256 + t;
        int ro = g >> 6, k = g & 63;
        int row = base + ro;
        float v = (row < N) ? emb[row * 64 + k] : 0.f;
        sf[ro * 68 + k] = v;
        ah[ro * 72 + k] = __float2half_rn(v);
    }
    __syncthreads();

    // ---- zero denom + edge histogram counters ----
    {
        int ro = t >> 2, q = t & 3;
        int node = base + ro;
        if (node < N) {
            g_denom[node * 4 + q] = 0.f;
            if (q == 0) g_cnt[node] = 0;
        }
    }

    // ---- proj via mma.sync m16n8k16 ----
    {
        int w = t >> 5, lane = t & 31;
        int gid = lane >> 2, tig = lane & 3;

        unsigned bfr[4][4][2];
        #pragma unroll
        for (int tn = 0; tn < 4; tn++) {
            int n = 32 * w + 8 * tn + gid;
            #pragma unroll
            for (int ks = 0; ks < 4; ks++) {
                bfr[tn][ks][0] = *(const unsigned*)&g_wfh[n * 64 + 16 * ks + 2 * tig];
                bfr[tn][ks][1] = *(const unsigned*)&g_wfh[n * 64 + 16 * ks + 2 * tig + 8];
            }
        }

        float acc[4][4][4];
        #pragma unroll
        for (int mg = 0; mg < 4; mg++)
            #pragma unroll
            for (int tn = 0; tn < 4; tn++)
                #pragma unroll
                for (int q = 0; q < 4; q++) acc[mg][tn][q] = 0.f;

        #pragma unroll
        for (int mg = 0; mg < 4; mg++) {
            int r0 = 16 * mg + gid;
            #pragma unroll
            for (int ks = 0; ks < 4; ks++) {
                unsigned a0 = *(const unsigned*)&ah[r0 * 72 + 16 * ks + 2 * tig];
                unsigned a1 = *(const unsigned*)&ah[(r0 + 8) * 72 + 16 * ks + 2 * tig];
                unsigned a2 = *(const unsigned*)&ah[r0 * 72 + 16 * ks + 2 * tig + 8];
                unsigned a3 = *(const unsigned*)&ah[(r0 + 8) * 72 + 16 * ks + 2 * tig + 8];
                #pragma unroll
                for (int tn = 0; tn < 4; tn++) {
                    asm("mma.sync.aligned.m16n8k16.row.col.f32.f16.f16.f32 "
                        "{%0,%1,%2,%3}, {%4,%5,%6,%7}, {%8,%9}, {%0,%1,%2,%3};"
                        : "+f"(acc[mg][tn][0]), "+f"(acc[mg][tn][1]),
                          "+f"(acc[mg][tn][2]), "+f"(acc[mg][tn][3])
                        : "r"(a0), "r"(a1), "r"(a2), "r"(a3),
                          "r"(bfr[tn][ks][0]), "r"(bfr[tn][ks][1]));
                }
            }
        }

        #pragma unroll
        for (int mg = 0; mg < 4; mg++) {
            #pragma unroll
            for (int tn = 0; tn < 4; tn++) {
                int j = 32 * w + 8 * tn + 2 * tig;
                int h = j >> 6, d = j & 63;
                int idx = 16 * (d >> 2) + 4 * h + (d & 3);
                int r = base + 16 * mg + gid;
                if (r < N) {
                    __half2 v = __floats2half2_rn(acc[mg][tn][0], acc[mg][tn][1]);
                    *(__half2*)&g_y2[(size_t)r * 256 + idx] = v;
                }
                if (r + 8 < N) {
                    __half2 v = __floats2half2_rn(acc[mg][tn][2], acc[mg][tn][3]);
                    *(__half2*)&g_y2[(size_t)(r + 8) * 256 + idx] = v;
                }
            }
        }
    }

    // ---- att logits (fp32) ----
    {
        int i = t >> 2, hh = t & 3;
        float as = 0.f, ad = 0.f;
        #pragma unroll 8
        for (int k = 0; k < 64; k++) {
            float e = sf[i * 68 + k];
            as = fmaf(e, s_w[k * 8 + hh], as);
            ad = fmaf(e, s_w[k * 8 + 4 + hh], ad);
        }
        int node = base + i;
        if (node < N) {
            g_asrc[node * 4 + hh] = as;
            g_adst[node * 4 + hh] = ad;
        }
    }
}

// ---------------- edge pass 1: ex, denom, dst histogram ----------------
__global__ void k_edge(const void* __restrict__ graph, int E, int ET) {
    int e = blockIdx.x * blockDim.x + threadIdx.x;
    if (e >= ET) return;
    int s, d;
    if (e < E) {
        if (g_is64) {
            const long long* g = (const long long*)graph;
            s = (int)g[e]; d = (int)g[E + e];
        } else {
            const int* g = (const int*)graph;
            s = g[e]; d = g[E + e];
        }
    } else {
        s = d = e - E;   // self loop
    }
    g_sd[e] = make_int2(s, d);

    float4 as4 = *(const float4*)&g_asrc[s * 4];
    float4 ad4 = *(const float4*)&g_adst[d * 4];
    float a0 = as4.x + ad4.x, a1 = as4.y + ad4.y, a2 = as4.z + ad4.z, a3 = as4.w + ad4.w;
    a0 = (a0 > 0.f) ? a0 : 0.2f * a0;
    a1 = (a1 > 0.f) ? a1 : 0.2f * a1;
    a2 = (a2 > 0.f) ? a2 : 0.2f * a2;
    a3 = (a3 > 0.f) ? a3 : 0.2f * a3;
    float4 ex4 = make_float4(__expf(a0), __expf(a1), __expf(a2), __expf(a3));
    *(float4*)&g_ex[e * 4] = ex4;

    float* dp = &g_denom[d * 4];
    asm volatile("red.global.v4.f32.add [%0], {%1, %2, %3, %4};"
                 :: "l"(dp), "f"(ex4.x), "f"(ex4.y), "f"(ex4.z), "f"(ex4.w)
                 : "memory");
    asm volatile("red.global.add.s32 [%0], 1;" :: "l"(&g_cnt[d]) : "memory");
}

// ---------------- scan: block-local shuffle scan + atomic block base --------
// Group bases need not be in node order — groups only need contiguity.
__global__ void __launch_bounds__(1024) k_scanA(int N) {
    __shared__ int wsum[32];
    __shared__ int baseSh;
    int t = threadIdx.x;
    int i = blockIdx.x * 1024 + t;
    int c = (i < N) ? g_cnt[i] : 0;

    int lane = t & 31, w = t >> 5;
    int incl = c;
    #pragma unroll
    for (int o = 1; o < 32; o <<= 1) {
        int u = __shfl_up_sync(0xffffffffu, incl, o);
        if (lane >= o) incl += u;
    }
    if (lane == 31) wsum[w] = incl;
    __syncthreads();
    if (w == 0) {
        int v = wsum[lane];
        #pragma unroll
        for (int o = 1; o < 32; o <<= 1) {
            int u = __shfl_up_sync(0xffffffffu, v, o);
            if (lane >= o) v += u;
        }
        wsum[lane] = v;
        if (lane == 31 && v > 0) baseSh = atomicAdd(&g_total, v);
        else if (lane == 31) baseSh = 0;
    }
    __syncthreads();
    int excl = incl - c + (w > 0 ? wsum[w - 1] : 0) + baseSh;
    if (i < N) {
        g_base[i] = excl;
        g_off[i]  = excl;
    }
}

// ---------------- place: dst-sorted packed meta {src, half4 coef} -----------
__global__ void k_place(int ET) {
    int e = blockIdx.x * blockDim.x + threadIdx.x;
    if (e >= ET) return;
    int2 sd = g_sd[e];
    float4 ex4 = *(const float4*)&g_ex[e * 4];
    float4 dn  = *(const float4*)&g_denom[sd.y * 4];
    float c0 = __fdividef(ex4.x, dn.x + 1e-16f);
    float c1 = __fdividef(ex4.y, dn.y + 1e-16f);
    float c2 = __fdividef(ex4.z, dn.z + 1e-16f);
    float c3 = __fdividef(ex4.w, dn.w + 1e-16f);
    __half2 c01 = __floats2half2_rn(c0, c1);
    __half2 c23 = __floats2half2_rn(c2, c3);
    uint4 m;
    m.x = (unsigned)sd.x;
    m.y = *(unsigned*)&c01;
    m.z = *(unsigned*)&c23;
    m.w = 0u;
    int pos = atomicAdd(&g_off[sd.y], 1);
    g_meta[pos] = m;
}

// ---------------- scatter2: 16 lanes per dst node, register accumulate ------
__global__ void __launch_bounds__(256) k_scatter2(float* __restrict__ out, int N) {
    int tid = blockIdx.x * blockDim.x + threadIdx.x;
    int g = tid >> 4, sub = tid & 15;
    if (g >= N) return;
    int base = g_base[g];
    int n = g_cnt[g];

    float4 acc = make_float4(0.f, 0.f, 0.f, 0.f);

    uint4 m_n = make_uint4(0u, 0u, 0u, 0u);
    if (n > 0) m_n = __ldg(&g_meta[base]);

    for (int i = 0; i < n; i++) {
        uint4 m = m_n;
        if (i + 1 < n) m_n = __ldg(&g_meta[base + i + 1]);

        int src = (int)m.x;
        float2 c01 = __half22float2(*(__half2*)&m.y);
        float2 c23 = __half22float2(*(__half2*)&m.z);

        const uint4* yp = (const uint4*)&g_y2[(size_t)src * 256];
        uint4 ua = __ldg(&yp[2 * sub]);
        uint4 ub = __ldg(&yp[2 * sub + 1]);

        float2 h0a = __half22float2(*(__half2*)&ua.x);
        float2 h0b = __half22float2(*(__half2*)&ua.y);
        float2 h1a = __half22float2(*(__half2*)&ua.z);
        float2 h1b = __half22float2(*(__half2*)&ua.w);
        float2 h2a = __half22float2(*(__half2*)&ub.x);
        float2 h2b = __half22float2(*(__half2*)&ub.y);
        float2 h3a = __half22float2(*(__half2*)&ub.z);
        float2 h3b = __half22float2(*(__half2*)&ub.w);

        acc.x += fmaf(c23.y, h3a.x, fmaf(c23.x, h2a.x, fmaf(c01.y, h1a.x, c01.x * h0a.x)));
        acc.y += fmaf(c23.y, h3a.y, fmaf(c23.x, h2a.y, fmaf(c01.y, h1a.y, c01.x * h0a.y)));
        acc.z += fmaf(c23.y, h3b.x, fmaf(c23.x, h2b.x, fmaf(c01.y, h1b.x, c01.x * h0b.x)));
        acc.w += fmaf(c23.y, h3b.y, fmaf(c23.x, h2b.y, fmaf(c01.y, h1b.y, c01.x * h0b.y)));
    }

    float4 b4 = *(const float4*)&g_b2[4 * sub];
    acc.x += b4.x; acc.y += b4.y; acc.z += b4.z; acc.w += b4.w;
    *(float4*)&out[(size_t)g * 64 + 4 * sub] = acc;
}

// ---------------- launch ----------------
extern "C" void kernel_launch(void* const* d_in, const int* in_sizes, int n_in,
                              void* d_out, int out_size) {
    const float* emb   = (const float*)d_in[0];
    const void*  graph = d_in[1];
    const float* W     = (const float*)d_in[2];
    const float* asr   = (const float*)d_in[3];
    const float* adt   = (const float*)d_in[4];
    const float* bias  = (const float*)d_in[5];
    const float* dw    = (const float*)d_in[6];
    const float* db    = (const float*)d_in[7];
    float* out = (float*)d_out;

    int N  = in_sizes[0] / 64;
    int E  = in_sizes[1] / 2;
    int ET = E + N;

    k_prep<<<266, 64>>>(W, dw, asr, adt, bias, db, (const int*)graph);
    k_phase1<<<(N + 63) / 64, 256>>>(emb, N);
    k_edge<<<(ET + 255) / 256, 256>>>(graph, E, ET);
    k_scanA<<<(N + 1023) / 1024, 1024>>>(N);
    k_place<<<(ET + 255) / 256, 256>>>(ET);
    k_scatter2<<<((size_t)N * 16 + 255) / 256, 256>>>(out, N);
}

// round 7
// speedup vs baseline: 1.5572x; 1.3496x over previous
#include <cuda_runtime.h>
#include <cuda_bf16.h>
#include <cuda_fp16.h>
#include <math.h>

#define NNODES 50000
#define NEDGES 800000
#define ETOT   (NEDGES + NNODES)

// ---------------- device scratch ----------------
__device__ __half g_y2[NNODES * 256];    // folded features fp16, scatter-packed:
                                         // y2[n][16*sub + 4*h + i] = y[n][h][4*sub+i]
__device__ float  g_asrc[NNODES * 4];
__device__ float  g_adst[NNODES * 4];
__device__ float  g_denom[NNODES * 4];
__device__ float  g_ex[ETOT * 4];
__device__ int2   g_sd[ETOT];
__device__ int    g_cnt[NNODES];         // edges per dst
__device__ int    g_base[NNODES];        // group start (node-ordered)
__device__ int    g_off[NNODES];         // placement cursor
__device__ int    g_bsum[64];            // per-block sums for scan
__device__ int    g_bofs[64];            // scanned block offsets
__device__ int    g_msrc[ETOT];          // dst-sorted: src
__device__ float4 g_mcoef[ETOT];         // dst-sorted: coef (fp32)
__device__ int    g_is64;
__device__ __half g_wfh[256 * 64];       // folded weights fp16, transposed [n][k]
__device__ float  g_ws[64 * 4];
__device__ float  g_wd[64 * 4];
__device__ float  g_b2[64];              // dense_b + bias @ dense_w

// ---------------- prep: folds + b2 + dtype detect ----------------
__global__ void __launch_bounds__(64) k_prep(const float* __restrict__ W,
                                             const float* __restrict__ dw,
                                             const float* __restrict__ asr,
                                             const float* __restrict__ adt,
                                             const float* __restrict__ bias,
                                             const float* __restrict__ db,
                                             const int* __restrict__ g32) {
    int b = blockIdx.x;
    int k = threadIdx.x;
    if (b < 256) {
        int j = b, h = j >> 6, d = j & 63;
        __shared__ float dcol[64];
        dcol[k] = dw[(h * 64 + k) * 64 + d];
        __syncthreads();
        const float4* wr = (const float4*)&W[k * 256 + h * 64];
        float acc = 0.f;
        #pragma unroll
        for (int q = 0; q < 16; q++) {
            float4 w4 = wr[q];
            acc = fmaf(w4.x, dcol[4 * q + 0], acc);
            acc = fmaf(w4.y, dcol[4 * q + 1], acc);
            acc = fmaf(w4.z, dcol[4 * q + 2], acc);
            acc = fmaf(w4.w, dcol[4 * q + 3], acc);
        }
        g_wfh[j * 64 + k] = __float2half_rn(acc);
    } else if (b < 264) {
        int bb = b - 256;
        int sel = bb >> 2, h = bb & 3;
        __shared__ float av[64];
        av[k] = sel ? adt[h * 64 + k] : asr[h * 64 + k];
        __syncthreads();
        const float4* wr = (const float4*)&W[k * 256 + h * 64];
        float acc = 0.f;
        #pragma unroll
        for (int q = 0; q < 16; q++) {
            float4 w4 = wr[q];
            acc = fmaf(w4.x, av[4 * q + 0], acc);
            acc = fmaf(w4.y, av[4 * q + 1], acc);
            acc = fmaf(w4.z, av[4 * q + 2], acc);
            acc = fmaf(w4.w, av[4 * q + 3], acc);
        }
        if (sel) g_wd[k * 4 + h] = acc; else g_ws[k * 4 + h] = acc;
    } else if (b == 264) {
        float acc = db[k];
        #pragma unroll 8
        for (int c = 0; c < 256; c++) acc = fmaf(bias[c], dw[c * 64 + k], acc);
        g_b2[k] = acc;
    } else {
        __shared__ int any_nonzero;
        if (k == 0) any_nonzero = 0;
        __syncthreads();
        int nz = 0;
        #pragma unroll
        for (int r = 0; r < 4; r++) nz |= g32[2 * (k + 64 * r) + 1];
        if (nz != 0) any_nonzero = 1;
        __syncthreads();
        if (k == 0) g_is64 = (any_nonzero == 0) ? 1 : 0;
    }
}

// ---------------- phase 1 (fused, HMMA): block = 64 nodes ----------------
__global__ void __launch_bounds__(256) k_phase1(const float* __restrict__ emb, int N) {
    __shared__ float  sf[64 * 68];
    __shared__ __half ah[64 * 72];
    __shared__ float  s_w[64 * 8];
    int t = threadIdx.x;
    int base = blockIdx.x * 64;

    for (int i = t; i < 512; i += 256) {
        int k = i >> 3, c = i & 7;
        s_w[i] = (c < 4) ? g_ws[k * 4 + c] : g_wd[k * 4 + (c - 4)];
    }
    #pragma unroll
    for (int j = 0; j < 16; j++) {
        int g = j * 256 + t;
        int ro = g >> 6, k = g & 63;
        int row = base + ro;
        float v = (row < N) ? emb[row * 64 + k] : 0.f;
        sf[ro * 68 + k] = v;
        ah[ro * 72 + k] = __float2half_rn(v);
    }
    __syncthreads();

    {
        int ro = t >> 2, q = t & 3;
        int node = base + ro;
        if (node < N) {
            g_denom[node * 4 + q] = 0.f;
            if (q == 0) g_cnt[node] = 0;
        }
    }

    {
        int w = t >> 5, lane = t & 31;
        int gid = lane >> 2, tig = lane & 3;

        unsigned bfr[4][4][2];
        #pragma unroll
        for (int tn = 0; tn < 4; tn++) {
            int n = 32 * w + 8 * tn + gid;
            #pragma unroll
            for (int ks = 0; ks < 4; ks++) {
                bfr[tn][ks][0] = *(const unsigned*)&g_wfh[n * 64 + 16 * ks + 2 * tig];
                bfr[tn][ks][1] = *(const unsigned*)&g_wfh[n * 64 + 16 * ks + 2 * tig + 8];
            }
        }

        float acc[4][4][4];
        #pragma unroll
        for (int mg = 0; mg < 4; mg++)
            #pragma unroll
            for (int tn = 0; tn < 4; tn++)
                #pragma unroll
                for (int q = 0; q < 4; q++) acc[mg][tn][q] = 0.f;

        #pragma unroll
        for (int mg = 0; mg < 4; mg++) {
            int r0 = 16 * mg + gid;
            #pragma unroll
            for (int ks = 0; ks < 4; ks++) {
                unsigned a0 = *(const unsigned*)&ah[r0 * 72 + 16 * ks + 2 * tig];
                unsigned a1 = *(const unsigned*)&ah[(r0 + 8) * 72 + 16 * ks + 2 * tig];
                unsigned a2 = *(const unsigned*)&ah[r0 * 72 + 16 * ks + 2 * tig + 8];
                unsigned a3 = *(const unsigned*)&ah[(r0 + 8) * 72 + 16 * ks + 2 * tig + 8];
                #pragma unroll
                for (int tn = 0; tn < 4; tn++) {
                    asm("mma.sync.aligned.m16n8k16.row.col.f32.f16.f16.f32 "
                        "{%0,%1,%2,%3}, {%4,%5,%6,%7}, {%8,%9}, {%0,%1,%2,%3};"
                        : "+f"(acc[mg][tn][0]), "+f"(acc[mg][tn][1]),
                          "+f"(acc[mg][tn][2]), "+f"(acc[mg][tn][3])
                        : "r"(a0), "r"(a1), "r"(a2), "r"(a3),
                          "r"(bfr[tn][ks][0]), "r"(bfr[tn][ks][1]));
                }
            }
        }

        #pragma unroll
        for (int mg = 0; mg < 4; mg++) {
            #pragma unroll
            for (int tn = 0; tn < 4; tn++) {
                int j = 32 * w + 8 * tn + 2 * tig;
                int h = j >> 6, d = j & 63;
                int idx = 16 * (d >> 2) + 4 * h + (d & 3);
                int r = base + 16 * mg + gid;
                if (r < N) {
                    __half2 v = __floats2half2_rn(acc[mg][tn][0], acc[mg][tn][1]);
                    *(__half2*)&g_y2[(size_t)r * 256 + idx] = v;
                }
                if (r + 8 < N) {
                    __half2 v = __floats2half2_rn(acc[mg][tn][2], acc[mg][tn][3]);
                    *(__half2*)&g_y2[(size_t)(r + 8) * 256 + idx] = v;
                }
            }
        }
    }

    {
        int i = t >> 2, hh = t & 3;
        float as = 0.f, ad = 0.f;
        #pragma unroll 8
        for (int k = 0; k < 64; k++) {
            float e = sf[i * 68 + k];
            as = fmaf(e, s_w[k * 8 + hh], as);
            ad = fmaf(e, s_w[k * 8 + 4 + hh], ad);
        }
        int node = base + i;
        if (node < N) {
            g_asrc[node * 4 + hh] = as;
            g_adst[node * 4 + hh] = ad;
        }
    }
}

// ---------------- edge pass 1: ex, denom, dst histogram ----------------
__global__ void k_edge(const void* __restrict__ graph, int E, int ET) {
    int e = blockIdx.x * blockDim.x + threadIdx.x;
    if (e >= ET) return;
    int s, d;
    if (e < E) {
        if (g_is64) {
            const long long* g = (const long long*)graph;
            s = (int)g[e]; d = (int)g[E + e];
        } else {
            const int* g = (const int*)graph;
            s = g[e]; d = g[E + e];
        }
    } else {
        s = d = e - E;   // self loop
    }
    g_sd[e] = make_int2(s, d);

    float4 as4 = *(const float4*)&g_asrc[s * 4];
    float4 ad4 = *(const float4*)&g_adst[d * 4];
    float a0 = as4.x + ad4.x, a1 = as4.y + ad4.y, a2 = as4.z + ad4.z, a3 = as4.w + ad4.w;
    a0 = (a0 > 0.f) ? a0 : 0.2f * a0;
    a1 = (a1 > 0.f) ? a1 : 0.2f * a1;
    a2 = (a2 > 0.f) ? a2 : 0.2f * a2;
    a3 = (a3 > 0.f) ? a3 : 0.2f * a3;
    float4 ex4 = make_float4(__expf(a0), __expf(a1), __expf(a2), __expf(a3));
    *(float4*)&g_ex[e * 4] = ex4;

    float* dp = &g_denom[d * 4];
    asm volatile("red.global.v4.f32.add [%0], {%1, %2, %3, %4};"
                 :: "l"(dp), "f"(ex4.x), "f"(ex4.y), "f"(ex4.z), "f"(ex4.w)
                 : "memory");
    asm volatile("red.global.add.s32 [%0], 1;" :: "l"(&g_cnt[d]) : "memory");
}

// ---------------- scan step A: block-local exclusive scan + block sums ------
__global__ void __launch_bounds__(1024) k_scanA(int N) {
    __shared__ int wsum[32];
    int t = threadIdx.x;
    int i = blockIdx.x * 1024 + t;
    int c = (i < N) ? g_cnt[i] : 0;

    int lane = t & 31, w = t >> 5;
    int incl = c;
    #pragma unroll
    for (int o = 1; o < 32; o <<= 1) {
        int u = __shfl_up_sync(0xffffffffu, incl, o);
        if (lane >= o) incl += u;
    }
    if (lane == 31) wsum[w] = incl;
    __syncthreads();
    if (w == 0) {
        int v = wsum[lane];
        #pragma unroll
        for (int o = 1; o < 32; o <<= 1) {
            int u = __shfl_up_sync(0xffffffffu, v, o);
            if (lane >= o) v += u;
        }
        wsum[lane] = v;
    }
    __syncthreads();
    int excl = incl - c + (w > 0 ? wsum[w - 1] : 0);
    if (i < N) g_base[i] = excl;
    if (t == 1023) g_bsum[blockIdx.x] = excl + c;   // block total
}

// ---------------- scan step B: exclusive scan over block sums (1 block) -----
__global__ void __launch_bounds__(64) k_scanB(int nb) {
    __shared__ int s[64];
    int t = threadIdx.x;
    int v = (t < nb) ? g_bsum[t] : 0;
    s[t] = v;
    __syncthreads();
    #pragma unroll
    for (int o = 1; o < 64; o <<= 1) {
        int u = (t >= o) ? s[t - o] : 0;
        __syncthreads();
        s[t] += u;
        __syncthreads();
    }
    if (t < nb) g_bofs[t] = s[t] - v;   // exclusive
}

// ---------------- scan step C: add block offsets ----------------
__global__ void __launch_bounds__(1024) k_scanC(int N) {
    int i = blockIdx.x * 1024 + threadIdx.x;
    if (i < N) {
        int b = g_base[i] + g_bofs[blockIdx.x];
        g_base[i] = b;
        g_off[i]  = b;
    }
}

// ---------------- place: dst-sorted {src, fp32 coef4} ----------------
__global__ void k_place(int ET) {
    int e = blockIdx.x * blockDim.x + threadIdx.x;
    if (e >= ET) return;
    int2 sd = g_sd[e];
    float4 ex4 = *(const float4*)&g_ex[e * 4];
    float4 dn  = *(const float4*)&g_denom[sd.y * 4];
    float4 c;
    c.x = __fdividef(ex4.x, dn.x + 1e-16f);
    c.y = __fdividef(ex4.y, dn.y + 1e-16f);
    c.z = __fdividef(ex4.z, dn.z + 1e-16f);
    c.w = __fdividef(ex4.w, dn.w + 1e-16f);
    int pos = atomicAdd(&g_off[sd.y], 1);
    g_msrc[pos] = sd.x;
    g_mcoef[pos] = c;
}

// ---------------- scatter2: WARP per dst node, 2 edges/iteration ------------
__global__ void __launch_bounds__(256) k_scatter2(float* __restrict__ out, int N) {
    int tid = blockIdx.x * blockDim.x + threadIdx.x;
    int g = tid >> 5;
    int lane = tid & 31;
    if (g >= N) return;
    int half = lane >> 4;        // 0: even edges, 1: odd edges
    int sub  = lane & 15;
    int base = g_base[g];
    int n = g_cnt[g];

    float4 acc = make_float4(0.f, 0.f, 0.f, 0.f);

    if (n > 0) {
        // prefetch iteration 0
        int j = half;
        int jc = (j < n) ? j : (n - 1);
        int   src_n = __ldg(&g_msrc[base + jc]);
        float4 c_n  = __ldg(&g_mcoef[base + jc]);
        bool  v_n   = (j < n);

        for (int i = 0; i < n; i += 2) {
            int   src = src_n;
            float4 c  = c_n;
            bool  v   = v_n;
            int nj = i + 2 + half;
            int njc = (nj < n) ? nj : (n - 1);
            src_n = __ldg(&g_msrc[base + njc]);
            c_n   = __ldg(&g_mcoef[base + njc]);
            v_n   = (nj < n);

            if (!v) { c.x = 0.f; c.y = 0.f; c.z = 0.f; c.w = 0.f; }

            const uint4* yp = (const uint4*)&g_y2[(size_t)src * 256];
            uint4 ua = __ldg(&yp[2 * sub]);
            uint4 ub = __ldg(&yp[2 * sub + 1]);

            float2 h0a = __half22float2(*(__half2*)&ua.x);
            float2 h0b = __half22float2(*(__half2*)&ua.y);
            float2 h1a = __half22float2(*(__half2*)&ua.z);
            float2 h1b = __half22float2(*(__half2*)&ua.w);
            float2 h2a = __half22float2(*(__half2*)&ub.x);
            float2 h2b = __half22float2(*(__half2*)&ub.y);
            float2 h3a = __half22float2(*(__half2*)&ub.z);
            float2 h3b = __half22float2(*(__half2*)&ub.w);

            acc.x += fmaf(c.w, h3a.x, fmaf(c.z, h2a.x, fmaf(c.y, h1a.x, c.x * h0a.x)));
            acc.y += fmaf(c.w, h3a.y, fmaf(c.z, h2a.y, fmaf(c.y, h1a.y, c.x * h0a.y)));
            acc.z += fmaf(c.w, h3b.x, fmaf(c.z, h2b.x, fmaf(c.y, h1b.x, c.x * h0b.x)));
            acc.w += fmaf(c.w, h3b.y, fmaf(c.z, h2b.y, fmaf(c.y, h1b.y, c.x * h0b.y)));
        }
    }

    // combine halves (lane l with l^16 share the same sub)
    acc.x += __shfl_xor_sync(0xffffffffu, acc.x, 16);
    acc.y += __shfl_xor_sync(0xffffffffu, acc.y, 16);
    acc.z += __shfl_xor_sync(0xffffffffu, acc.z, 16);
    acc.w += __shfl_xor_sync(0xffffffffu, acc.w, 16);

    if (half == 0) {
        float4 b4 = *(const float4*)&g_b2[4 * sub];
        acc.x += b4.x; acc.y += b4.y; acc.z += b4.z; acc.w += b4.w;
        *(float4*)&out[(size_t)g * 64 + 4 * sub] = acc;
    }
}

// ---------------- launch ----------------
extern "C" void kernel_launch(void* const* d_in, const int* in_sizes, int n_in,
                              void* d_out, int out_size) {
    const float* emb   = (const float*)d_in[0];
    const void*  graph = d_in[1];
    const float* W     = (const float*)d_in[2];
    const float* asr   = (const float*)d_in[3];
    const float* adt   = (const float*)d_in[4];
    const float* bias  = (const float*)d_in[5];
    const float* dw    = (const float*)d_in[6];
    const float* db    = (const float*)d_in[7];
    float* out = (float*)d_out;

    int N  = in_sizes[0] / 64;
    int E  = in_sizes[1] / 2;
    int ET = E + N;
    int nb = (N + 1023) / 1024;

    k_prep<<<266, 64>>>(W, dw, asr, adt, bias, db, (const int*)graph);
    k_phase1<<<(N + 63) / 64, 256>>>(emb, N);
    k_edge<<<(ET + 255) / 256, 256>>>(graph, E, ET);
    k_scanA<<<nb, 1024>>>(N);
    k_scanB<<<1, 64>>>(nb);
    k_scanC<<<nb, 1024>>>(N);
    k_place<<<(ET + 255) / 256, 256>>>(ET);
    k_scatter2<<<((size_t)N * 32 + 255) / 256, 256>>>(out, N);
}

// round 8
// speedup vs baseline: 1.6324x; 1.0483x over previous
#include <cuda_runtime.h>
#include <cuda_bf16.h>
#include <cuda_fp16.h>
#include <math.h>

#define NNODES 50000
#define NEDGES 800000
#define ETOT   (NEDGES + NNODES)

// ---------------- device scratch ----------------
__device__ __half g_y2[NNODES * 256];    // folded features fp16, scatter-packed:
                                         // y2[n][16*sub + 4*h + i] = y[n][h][4*sub+i]
__device__ float  g_asrc[NNODES * 4];
__device__ float  g_adst[NNODES * 4];
__device__ float  g_denom[NNODES * 4];
__device__ int    g_cnt[NNODES];         // edges per dst
__device__ int    g_base[NNODES];        // group start (node-ordered)
__device__ int    g_off[NNODES];         // placement cursor
__device__ int    g_bsum[64];
__device__ int    g_bofs[64];
__device__ int    g_msrc[ETOT];          // dst-sorted: src
__device__ float4 g_mex[ETOT];           // dst-sorted: exp(leaky(alpha)) per head
__device__ int    g_is64;
__device__ __half g_wfh[256 * 64];       // folded weights fp16, transposed [n][k]
__device__ float  g_ws[64 * 4];
__device__ float  g_wd[64 * 4];
__device__ float  g_b2[64];              // dense_b + bias @ dense_w

// ---------------- prep: folds + b2 + dtype detect ----------------
__global__ void __launch_bounds__(64) k_prep(const float* __restrict__ W,
                                             const float* __restrict__ dw,
                                             const float* __restrict__ asr,
                                             const float* __restrict__ adt,
                                             const float* __restrict__ bias,
                                             const float* __restrict__ db,
                                             const int* __restrict__ g32) {
    int b = blockIdx.x;
    int k = threadIdx.x;
    if (b < 256) {
        int j = b, h = j >> 6, d = j & 63;
        __shared__ float dcol[64];
        dcol[k] = dw[(h * 64 + k) * 64 + d];
        __syncthreads();
        const float4* wr = (const float4*)&W[k * 256 + h * 64];
        float acc = 0.f;
        #pragma unroll
        for (int q = 0; q < 16; q++) {
            float4 w4 = wr[q];
            acc = fmaf(w4.x, dcol[4 * q + 0], acc);
            acc = fmaf(w4.y, dcol[4 * q + 1], acc);
            acc = fmaf(w4.z, dcol[4 * q + 2], acc);
            acc = fmaf(w4.w, dcol[4 * q + 3], acc);
        }
        g_wfh[j * 64 + k] = __float2half_rn(acc);
    } else if (b < 264) {
        int bb = b - 256;
        int sel = bb >> 2, h = bb & 3;
        __shared__ float av[64];
        av[k] = sel ? adt[h * 64 + k] : asr[h * 64 + k];
        __syncthreads();
        const float4* wr = (const float4*)&W[k * 256 + h * 64];
        float acc = 0.f;
        #pragma unroll
        for (int q = 0; q < 16; q++) {
            float4 w4 = wr[q];
            acc = fmaf(w4.x, av[4 * q + 0], acc);
            acc = fmaf(w4.y, av[4 * q + 1], acc);
            acc = fmaf(w4.z, av[4 * q + 2], acc);
            acc = fmaf(w4.w, av[4 * q + 3], acc);
        }
        if (sel) g_wd[k * 4 + h] = acc; else g_ws[k * 4 + h] = acc;
    } else if (b == 264) {
        float acc = db[k];
        #pragma unroll 8
        for (int c = 0; c < 256; c++) acc = fmaf(bias[c], dw[c * 64 + k], acc);
        g_b2[k] = acc;
    } else {
        __shared__ int any_nonzero;
        if (k == 0) any_nonzero = 0;
        __syncthreads();
        int nz = 0;
        #pragma unroll
        for (int r = 0; r < 4; r++) nz |= g32[2 * (k + 64 * r) + 1];
        if (nz != 0) any_nonzero = 1;
        __syncthreads();
        if (k == 0) g_is64 = (any_nonzero == 0) ? 1 : 0;
    }
}

// ---------------- phase 1 (fused, HMMA), coalesced y2 stores ----------------
__global__ void __launch_bounds__(256) k_phase1(const float* __restrict__ emb, int N) {
    __shared__ float  sf[64 * 68];     // fp32 emb tile
    __shared__ __half ah[64 * 72];     // fp16 emb tile
    __shared__ float  s_w[64 * 8];
    __shared__ __half sy[32 * 264];    // y2 staging (32 rows, padded stride)
    int t = threadIdx.x;
    int base = blockIdx.x * 64;

    for (int i = t; i < 512; i += 256) {
        int k = i >> 3, c = i & 7;
        s_w[i] = (c < 4) ? g_ws[k * 4 + c] : g_wd[k * 4 + (c - 4)];
    }
    #pragma unroll
    for (int j = 0; j < 16; j++) {
        int g = j * 256 + t;
        int ro = g >> 6, k = g & 63;
        int row = base + ro;
        float v = (row < N) ? emb[row * 64 + k] : 0.f;
        sf[ro * 68 + k] = v;
        ah[ro * 72 + k] = __float2half_rn(v);
    }
    __syncthreads();

    // zero denom + cnt
    {
        int ro = t >> 2, q = t & 3;
        int node = base + ro;
        if (node < N) {
            g_denom[node * 4 + q] = 0.f;
            if (q == 0) g_cnt[node] = 0;
        }
    }

    int w = t >> 5, lane = t & 31;
    int gid = lane >> 2, tig = lane & 3;

    // ---- MMA ----
    float acc[4][4][4];
    {
        unsigned bfr[4][4][2];
        #pragma unroll
        for (int tn = 0; tn < 4; tn++) {
            int n = 32 * w + 8 * tn + gid;
            #pragma unroll
            for (int ks = 0; ks < 4; ks++) {
                bfr[tn][ks][0] = *(const unsigned*)&g_wfh[n * 64 + 16 * ks + 2 * tig];
                bfr[tn][ks][1] = *(const unsigned*)&g_wfh[n * 64 + 16 * ks + 2 * tig + 8];
            }
        }
        #pragma unroll
        for (int mg = 0; mg < 4; mg++)
            #pragma unroll
            for (int tn = 0; tn < 4; tn++)
                #pragma unroll
                for (int q = 0; q < 4; q++) acc[mg][tn][q] = 0.f;

        #pragma unroll
        for (int mg = 0; mg < 4; mg++) {
            int r0 = 16 * mg + gid;
            #pragma unroll
            for (int ks = 0; ks < 4; ks++) {
                unsigned a0 = *(const unsigned*)&ah[r0 * 72 + 16 * ks + 2 * tig];
                unsigned a1 = *(const unsigned*)&ah[(r0 + 8) * 72 + 16 * ks + 2 * tig];
                unsigned a2 = *(const unsigned*)&ah[r0 * 72 + 16 * ks + 2 * tig + 8];
                unsigned a3 = *(const unsigned*)&ah[(r0 + 8) * 72 + 16 * ks + 2 * tig + 8];
                #pragma unroll
                for (int tn = 0; tn < 4; tn++) {
                    asm("mma.sync.aligned.m16n8k16.row.col.f32.f16.f16.f32 "
                        "{%0,%1,%2,%3}, {%4,%5,%6,%7}, {%8,%9}, {%0,%1,%2,%3};"
                        : "+f"(acc[mg][tn][0]), "+f"(acc[mg][tn][1]),
                          "+f"(acc[mg][tn][2]), "+f"(acc[mg][tn][3])
                        : "r"(a0), "r"(a1), "r"(a2), "r"(a3),
                          "r"(bfr[tn][ks][0]), "r"(bfr[tn][ks][1]));
                }
            }
        }
    }

    // ---- att logits (fp32) ----
    {
        int i = t >> 2, hh = t & 3;
        float as = 0.f, ad = 0.f;
        #pragma unroll 8
        for (int k = 0; k < 64; k++) {
            float e = sf[i * 68 + k];
            as = fmaf(e, s_w[k * 8 + hh], as);
            ad = fmaf(e, s_w[k * 8 + 4 + hh], ad);
        }
        int node = base + i;
        if (node < N) {
            g_asrc[node * 4 + hh] = as;
            g_adst[node * 4 + hh] = ad;
        }
    }

    // ---- y2 stores via smem staging, 32 rows per pass, coalesced out ----
    #pragma unroll
    for (int p = 0; p < 2; p++) {
        __syncthreads();
        #pragma unroll
        for (int mgl = 0; mgl < 2; mgl++) {
            int mg = 2 * p + mgl;
            #pragma unroll
            for (int tn = 0; tn < 4; tn++) {
                int j = 32 * w + 8 * tn + 2 * tig;
                int h = j >> 6, d = j & 63;
                int idx = 16 * (d >> 2) + 4 * h + (d & 3);
                int rl = 16 * mg + gid - 32 * p;   // 0..23 within pass
                __half2 v0 = __floats2half2_rn(acc[mg][tn][0], acc[mg][tn][1]);
                __half2 v1 = __floats2half2_rn(acc[mg][tn][2], acc[mg][tn][3]);
                *(__half2*)&sy[rl * 264 + idx] = v0;
                *(__half2*)&sy[(rl + 8) * 264 + idx] = v1;
            }
        }
        __syncthreads();
        // copy out: warp per row-quad, 512B contiguous per row
        int q = t & 31;
        #pragma unroll
        for (int rr8 = 0; rr8 < 4; rr8++) {
            int rr = (t >> 5) + 8 * rr8;
            int row = base + 32 * p + rr;
            if (row < N)
                ((uint4*)&g_y2[(size_t)row * 256])[q] = *(uint4*)&sy[rr * 264 + 8 * q];
        }
    }
}

// ---------------- hist: edges per dst ----------------
__global__ void k_hist(const void* __restrict__ graph, int E, int ET) {
    int e = blockIdx.x * blockDim.x + threadIdx.x;
    if (e >= ET) return;
    int d;
    if (e < E) {
        if (g_is64) d = (int)((const long long*)graph)[E + e];
        else        d = ((const int*)graph)[E + e];
    } else {
        d = e - E;
    }
    asm volatile("red.global.add.s32 [%0], 1;" :: "l"(&g_cnt[d]) : "memory");
}

// ---------------- scan A/B/C (node-ordered bases) ----------------
__global__ void __launch_bounds__(1024) k_scanA(int N) {
    __shared__ int wsum[32];
    int t = threadIdx.x;
    int i = blockIdx.x * 1024 + t;
    int c = (i < N) ? g_cnt[i] : 0;
    int lane = t & 31, w = t >> 5;
    int incl = c;
    #pragma unroll
    for (int o = 1; o < 32; o <<= 1) {
        int u = __shfl_up_sync(0xffffffffu, incl, o);
        if (lane >= o) incl += u;
    }
    if (lane == 31) wsum[w] = incl;
    __syncthreads();
    if (w == 0) {
        int v = wsum[lane];
        #pragma unroll
        for (int o = 1; o < 32; o <<= 1) {
            int u = __shfl_up_sync(0xffffffffu, v, o);
            if (lane >= o) v += u;
        }
        wsum[lane] = v;
    }
    __syncthreads();
    int excl = incl - c + (w > 0 ? wsum[w - 1] : 0);
    if (i < N) g_base[i] = excl;
    if (t == 1023) g_bsum[blockIdx.x] = excl + c;
}

__global__ void __launch_bounds__(64) k_scanB(int nb) {
    __shared__ int s[64];
    int t = threadIdx.x;
    int v = (t < nb) ? g_bsum[t] : 0;
    s[t] = v;
    __syncthreads();
    #pragma unroll
    for (int o = 1; o < 64; o <<= 1) {
        int u = (t >= o) ? s[t - o] : 0;
        __syncthreads();
        s[t] += u;
        __syncthreads();
    }
    if (t < nb) g_bofs[t] = s[t] - v;
}

__global__ void __launch_bounds__(1024) k_scanC(int N) {
    int i = blockIdx.x * 1024 + threadIdx.x;
    if (i < N) {
        int b = g_base[i] + g_bofs[blockIdx.x];
        g_base[i] = b;
        g_off[i]  = b;
    }
}

// ---------------- edge2: ex + denom RED + meta placement (fused) ------------
__global__ void k_edge2(const void* __restrict__ graph, int E, int ET) {
    int e = blockIdx.x * blockDim.x + threadIdx.x;
    if (e >= ET) return;
    int s, d;
    if (e < E) {
        if (g_is64) {
            const long long* g = (const long long*)graph;
            s = (int)g[e]; d = (int)g[E + e];
        } else {
            const int* g = (const int*)graph;
            s = g[e]; d = g[E + e];
        }
    } else {
        s = d = e - E;   // self loop
    }

    float4 as4 = *(const float4*)&g_asrc[s * 4];
    float4 ad4 = *(const float4*)&g_adst[d * 4];
    float a0 = as4.x + ad4.x, a1 = as4.y + ad4.y, a2 = as4.z + ad4.z, a3 = as4.w + ad4.w;
    a0 = (a0 > 0.f) ? a0 : 0.2f * a0;
    a1 = (a1 > 0.f) ? a1 : 0.2f * a1;
    a2 = (a2 > 0.f) ? a2 : 0.2f * a2;
    a3 = (a3 > 0.f) ? a3 : 0.2f * a3;
    float4 ex4 = make_float4(__expf(a0), __expf(a1), __expf(a2), __expf(a3));

    float* dp = &g_denom[d * 4];
    asm volatile("red.global.v4.f32.add [%0], {%1, %2, %3, %4};"
                 :: "l"(dp), "f"(ex4.x), "f"(ex4.y), "f"(ex4.z), "f"(ex4.w)
                 : "memory");
    int pos = atomicAdd(&g_off[d], 1);
    g_msrc[pos] = s;
    g_mex[pos]  = ex4;
}

// ---------------- scatter2: WARP per dst node, 2 edges/iter, /denom at end --
__global__ void __launch_bounds__(256) k_scatter2(float* __restrict__ out, int N) {
    int tid = blockIdx.x * blockDim.x + threadIdx.x;
    int g = tid >> 5;
    int lane = tid & 31;
    if (g >= N) return;
    int half = lane >> 4;
    int sub  = lane & 15;
    int base = g_base[g];
    int n = g_cnt[g];

    float4 dn = *(const float4*)&g_denom[g * 4];
    float4 rdn;
    rdn.x = __fdividef(1.f, dn.x + 1e-16f);
    rdn.y = __fdividef(1.f, dn.y + 1e-16f);
    rdn.z = __fdividef(1.f, dn.z + 1e-16f);
    rdn.w = __fdividef(1.f, dn.w + 1e-16f);

    float4 acc = make_float4(0.f, 0.f, 0.f, 0.f);

    if (n > 0) {
        int j = half;
        int jc = (j < n) ? j : (n - 1);
        int    src_n = __ldg(&g_msrc[base + jc]);
        float4 ex_n  = __ldg(&g_mex[base + jc]);
        bool   v_n   = (j < n);

        for (int i = 0; i < n; i += 2) {
            int    src = src_n;
            float4 ex  = ex_n;
            bool   v   = v_n;
            int nj = i + 2 + half;
            int njc = (nj < n) ? nj : (n - 1);
            src_n = __ldg(&g_msrc[base + njc]);
            ex_n  = __ldg(&g_mex[base + njc]);
            v_n   = (nj < n);

            float4 c;
            c.x = v ? ex.x * rdn.x : 0.f;
            c.y = v ? ex.y * rdn.y : 0.f;
            c.z = v ? ex.z * rdn.z : 0.f;
            c.w = v ? ex.w * rdn.w : 0.f;

            const uint4* yp = (const uint4*)&g_y2[(size_t)src * 256];
            uint4 ua = __ldg(&yp[2 * sub]);
            uint4 ub = __ldg(&yp[2 * sub + 1]);

            float2 h0a = __half22float2(*(__half2*)&ua.x);
            float2 h0b = __half22float2(*(__half2*)&ua.y);
            float2 h1a = __half22float2(*(__half2*)&ua.z);
            float2 h1b = __half22float2(*(__half2*)&ua.w);
            float2 h2a = __half22float2(*(__half2*)&ub.x);
            float2 h2b = __half22float2(*(__half2*)&ub.y);
            float2 h3a = __half22float2(*(__half2*)&ub.z);
            float2 h3b = __half22float2(*(__half2*)&ub.w);

            acc.x += fmaf(c.w, h3a.x, fmaf(c.z, h2a.x, fmaf(c.y, h1a.x, c.x * h0a.x)));
            acc.y += fmaf(c.w, h3a.y, fmaf(c.z, h2a.y, fmaf(c.y, h1a.y, c.x * h0a.y)));
            acc.z += fmaf(c.w, h3b.x, fmaf(c.z, h2b.x, fmaf(c.y, h1b.x, c.x * h0b.x)));
            acc.w += fmaf(c.w, h3b.y, fmaf(c.z, h2b.y, fmaf(c.y, h1b.y, c.x * h0b.y)));
        }
    }

    acc.x += __shfl_xor_sync(0xffffffffu, acc.x, 16);
    acc.y += __shfl_xor_sync(0xffffffffu, acc.y, 16);
    acc.z += __shfl_xor_sync(0xffffffffu, acc.z, 16);
    acc.w += __shfl_xor_sync(0xffffffffu, acc.w, 16);

    if (half == 0) {
        float4 b4 = *(const float4*)&g_b2[4 * sub];
        acc.x += b4.x; acc.y += b4.y; acc.z += b4.z; acc.w += b4.w;
        *(float4*)&out[(size_t)g * 64 + 4 * sub] = acc;
    }
}

// ---------------- launch ----------------
extern "C" void kernel_launch(void* const* d_in, const int* in_sizes, int n_in,
                              void* d_out, int out_size) {
    const float* emb   = (const float*)d_in[0];
    const void*  graph = d_in[1];
    const float* W     = (const float*)d_in[2];
    const float* asr   = (const float*)d_in[3];
    const float* adt   = (const float*)d_in[4];
    const float* bias  = (const float*)d_in[5];
    const float* dw    = (const float*)d_in[6];
    const float* db    = (const float*)d_in[7];
    float* out = (float*)d_out;

    int N  = in_sizes[0] / 64;
    int E  = in_sizes[1] / 2;
    int ET = E + N;
    int nb = (N + 1023) / 1024;

    k_prep<<<266, 64>>>(W, dw, asr, adt, bias, db, (const int*)graph);
    k_phase1<<<(N + 63) / 64, 256>>>(emb, N);
    k_hist<<<(ET + 255) / 256, 256>>>(graph, E, ET);
    k_scanA<<<nb, 1024>>>(N);
    k_scanB<<<1, 64>>>(nb);
    k_scanC<<<nb, 1024>>>(N);
    k_edge2<<<(ET + 255) / 256, 256>>>(graph, E, ET);
    k_scatter2<<<((size_t)N * 32 + 255) / 256, 256>>>(out, N);
}

// round 9
// speedup vs baseline: 1.7931x; 1.0984x over previous
#include <cuda_runtime.h>
#include <cuda_bf16.h>
#include <cuda_fp16.h>
#include <math.h>

#define NNODES 50000
#define NEDGES 800000
#define ETOT   (NEDGES + NNODES)

// ---------------- device scratch ----------------
__device__ __half g_y2[NNODES * 256];    // folded features fp16, scatter-packed
__device__ float  g_asrc[NNODES * 4];
__device__ float  g_adst[NNODES * 4];
__device__ int    g_cnt[NNODES];         // edges per dst
__device__ int    g_base[NNODES];        // group start (node-ordered)
__device__ int    g_off[NNODES];         // placement cursor
__device__ int    g_bsum[64];
__device__ int    g_bofs[64];
__device__ int    g_msrc[ETOT];          // dst-sorted: src
__device__ float4 g_mex[ETOT];           // dst-sorted: exp(leaky(alpha))
__device__ int    g_is64;
__device__ __half g_wfh[256 * 64];       // folded weights fp16, transposed [n][k]
__device__ float  g_ws[64 * 4];
__device__ float  g_wd[64 * 4];
__device__ float  g_b2[64];              // dense_b + bias @ dense_w

// ---------------- prep: folds + b2 + dtype detect + zero cnt ----------------
__global__ void __launch_bounds__(64) k_prep(const float* __restrict__ W,
                                             const float* __restrict__ dw,
                                             const float* __restrict__ asr,
                                             const float* __restrict__ adt,
                                             const float* __restrict__ bias,
                                             const float* __restrict__ db,
                                             const int* __restrict__ g32, int N) {
    int b = blockIdx.x;
    int k = threadIdx.x;
    if (b < 256) {
        int j = b, h = j >> 6, d = j & 63;
        __shared__ float dcol[64];
        dcol[k] = dw[(h * 64 + k) * 64 + d];
        __syncthreads();
        const float4* wr = (const float4*)&W[k * 256 + h * 64];
        float acc = 0.f;
        #pragma unroll
        for (int q = 0; q < 16; q++) {
            float4 w4 = wr[q];
            acc = fmaf(w4.x, dcol[4 * q + 0], acc);
            acc = fmaf(w4.y, dcol[4 * q + 1], acc);
            acc = fmaf(w4.z, dcol[4 * q + 2], acc);
            acc = fmaf(w4.w, dcol[4 * q + 3], acc);
        }
        g_wfh[j * 64 + k] = __float2half_rn(acc);
    } else if (b < 264) {
        int bb = b - 256;
        int sel = bb >> 2, h = bb & 3;
        __shared__ float av[64];
        av[k] = sel ? adt[h * 64 + k] : asr[h * 64 + k];
        __syncthreads();
        const float4* wr = (const float4*)&W[k * 256 + h * 64];
        float acc = 0.f;
        #pragma unroll
        for (int q = 0; q < 16; q++) {
            float4 w4 = wr[q];
            acc = fmaf(w4.x, av[4 * q + 0], acc);
            acc = fmaf(w4.y, av[4 * q + 1], acc);
            acc = fmaf(w4.z, av[4 * q + 2], acc);
            acc = fmaf(w4.w, av[4 * q + 3], acc);
        }
        if (sel) g_wd[k * 4 + h] = acc; else g_ws[k * 4 + h] = acc;
    } else if (b == 264) {
        float acc = db[k];
        #pragma unroll 8
        for (int c = 0; c < 256; c++) acc = fmaf(bias[c], dw[c * 64 + k], acc);
        g_b2[k] = acc;
    } else if (b == 265) {
        __shared__ int any_nonzero;
        if (k == 0) any_nonzero = 0;
        __syncthreads();
        int nz = 0;
        #pragma unroll
        for (int r = 0; r < 4; r++) nz |= g32[2 * (k + 64 * r) + 1];
        if (nz != 0) any_nonzero = 1;
        __syncthreads();
        if (k == 0) g_is64 = (any_nonzero == 0) ? 1 : 0;
    } else {
        int i = (b - 266) * 64 + k;
        if (i < N) g_cnt[i] = 0;
    }
}

// ---------------- phase1 (HMMA proj + att) PARALLEL WITH hist ---------------
__global__ void __launch_bounds__(256) k_phase1h(const float* __restrict__ emb,
                                                 const void* __restrict__ graph,
                                                 int N, int E, int ET, int P) {
    __shared__ float  sf[64 * 68];
    __shared__ __half ah[64 * 72];
    __shared__ float  s_w[64 * 8];
    __shared__ __half sy[32 * 264];
    int t = threadIdx.x;

    if (blockIdx.x >= P) {
        // ---- hist branch: edges per dst ----
        int e = (blockIdx.x - P) * 256 + t;
        if (e < ET) {
            int d;
            if (e < E) {
                if (g_is64) d = (int)((const long long*)graph)[E + e];
                else        d = ((const int*)graph)[E + e];
            } else {
                d = e - E;
            }
            asm volatile("red.global.add.s32 [%0], 1;" :: "l"(&g_cnt[d]) : "memory");
        }
        return;
    }

    int base = blockIdx.x * 64;

    for (int i = t; i < 512; i += 256) {
        int k = i >> 3, c = i & 7;
        s_w[i] = (c < 4) ? g_ws[k * 4 + c] : g_wd[k * 4 + (c - 4)];
    }
    #pragma unroll
    for (int j = 0; j < 16; j++) {
        int g = j * 256 + t;
        int ro = g >> 6, k = g & 63;
        int row = base + ro;
        float v = (row < N) ? emb[row * 64 + k] : 0.f;
        sf[ro * 68 + k] = v;
        ah[ro * 72 + k] = __float2half_rn(v);
    }
    __syncthreads();

    int w = t >> 5, lane = t & 31;
    int gid = lane >> 2, tig = lane & 3;

    // ---- MMA ----
    float acc[4][4][4];
    {
        unsigned bfr[4][4][2];
        #pragma unroll
        for (int tn = 0; tn < 4; tn++) {
            int n = 32 * w + 8 * tn + gid;
            #pragma unroll
            for (int ks = 0; ks < 4; ks++) {
                bfr[tn][ks][0] = *(const unsigned*)&g_wfh[n * 64 + 16 * ks + 2 * tig];
                bfr[tn][ks][1] = *(const unsigned*)&g_wfh[n * 64 + 16 * ks + 2 * tig + 8];
            }
        }
        #pragma unroll
        for (int mg = 0; mg < 4; mg++)
            #pragma unroll
            for (int tn = 0; tn < 4; tn++)
                #pragma unroll
                for (int q = 0; q < 4; q++) acc[mg][tn][q] = 0.f;

        #pragma unroll
        for (int mg = 0; mg < 4; mg++) {
            int r0 = 16 * mg + gid;
            #pragma unroll
            for (int ks = 0; ks < 4; ks++) {
                unsigned a0 = *(const unsigned*)&ah[r0 * 72 + 16 * ks + 2 * tig];
                unsigned a1 = *(const unsigned*)&ah[(r0 + 8) * 72 + 16 * ks + 2 * tig];
                unsigned a2 = *(const unsigned*)&ah[r0 * 72 + 16 * ks + 2 * tig + 8];
                unsigned a3 = *(const unsigned*)&ah[(r0 + 8) * 72 + 16 * ks + 2 * tig + 8];
                #pragma unroll
                for (int tn = 0; tn < 4; tn++) {
                    asm("mma.sync.aligned.m16n8k16.row.col.f32.f16.f16.f32 "
                        "{%0,%1,%2,%3}, {%4,%5,%6,%7}, {%8,%9}, {%0,%1,%2,%3};"
                        : "+f"(acc[mg][tn][0]), "+f"(acc[mg][tn][1]),
                          "+f"(acc[mg][tn][2]), "+f"(acc[mg][tn][3])
                        : "r"(a0), "r"(a1), "r"(a2), "r"(a3),
                          "r"(bfr[tn][ks][0]), "r"(bfr[tn][ks][1]));
                }
            }
        }
    }

    // ---- att logits (fp32) ----
    {
        int i = t >> 2, hh = t & 3;
        float as = 0.f, ad = 0.f;
        #pragma unroll 8
        for (int k = 0; k < 64; k++) {
            float e = sf[i * 68 + k];
            as = fmaf(e, s_w[k * 8 + hh], as);
            ad = fmaf(e, s_w[k * 8 + 4 + hh], ad);
        }
        int node = base + i;
        if (node < N) {
            g_asrc[node * 4 + hh] = as;
            g_adst[node * 4 + hh] = ad;
        }
    }

    // ---- y2 stores via smem staging, coalesced ----
    #pragma unroll
    for (int p = 0; p < 2; p++) {
        __syncthreads();
        #pragma unroll
        for (int mgl = 0; mgl < 2; mgl++) {
            int mg = 2 * p + mgl;
            #pragma unroll
            for (int tn = 0; tn < 4; tn++) {
                int j = 32 * w + 8 * tn + 2 * tig;
                int h = j >> 6, d = j & 63;
                int idx = 16 * (d >> 2) + 4 * h + (d & 3);
                int rl = 16 * mg + gid - 32 * p;
                __half2 v0 = __floats2half2_rn(acc[mg][tn][0], acc[mg][tn][1]);
                __half2 v1 = __floats2half2_rn(acc[mg][tn][2], acc[mg][tn][3]);
                *(__half2*)&sy[rl * 264 + idx] = v0;
                *(__half2*)&sy[(rl + 8) * 264 + idx] = v1;
            }
        }
        __syncthreads();
        int q = t & 31;
        #pragma unroll
        for (int rr8 = 0; rr8 < 4; rr8++) {
            int rr = (t >> 5) + 8 * rr8;
            int row = base + 32 * p + rr;
            if (row < N)
                ((uint4*)&g_y2[(size_t)row * 256])[q] = *(uint4*)&sy[rr * 264 + 8 * q];
        }
    }
}

// ---------------- scan A/B/C (node-ordered bases) ----------------
__global__ void __launch_bounds__(1024) k_scanA(int N) {
    __shared__ int wsum[32];
    int t = threadIdx.x;
    int i = blockIdx.x * 1024 + t;
    int c = (i < N) ? g_cnt[i] : 0;
    int lane = t & 31, w = t >> 5;
    int incl = c;
    #pragma unroll
    for (int o = 1; o < 32; o <<= 1) {
        int u = __shfl_up_sync(0xffffffffu, incl, o);
        if (lane >= o) incl += u;
    }
    if (lane == 31) wsum[w] = incl;
    __syncthreads();
    if (w == 0) {
        int v = wsum[lane];
        #pragma unroll
        for (int o = 1; o < 32; o <<= 1) {
            int u = __shfl_up_sync(0xffffffffu, v, o);
            if (lane >= o) v += u;
        }
        wsum[lane] = v;
    }
    __syncthreads();
    int excl = incl - c + (w > 0 ? wsum[w - 1] : 0);
    if (i < N) g_base[i] = excl;
    if (t == 1023) g_bsum[blockIdx.x] = excl + c;
}

__global__ void __launch_bounds__(64) k_scanB(int nb) {
    __shared__ int s[64];
    int t = threadIdx.x;
    int v = (t < nb) ? g_bsum[t] : 0;
    s[t] = v;
    __syncthreads();
    #pragma unroll
    for (int o = 1; o < 64; o <<= 1) {
        int u = (t >= o) ? s[t - o] : 0;
        __syncthreads();
        s[t] += u;
        __syncthreads();
    }
    if (t < nb) g_bofs[t] = s[t] - v;
}

__global__ void __launch_bounds__(1024) k_scanC(int N) {
    int i = blockIdx.x * 1024 + threadIdx.x;
    if (i < N) {
        int b = g_base[i] + g_bofs[blockIdx.x];
        g_base[i] = b;
        g_off[i]  = b;
    }
}

// ---------------- edge2: ex + meta placement (no denom RED) ----------------
__global__ void k_edge2(const void* __restrict__ graph, int E, int ET) {
    int e = blockIdx.x * blockDim.x + threadIdx.x;
    if (e >= ET) return;
    int s, d;
    if (e < E) {
        if (g_is64) {
            const long long* g = (const long long*)graph;
            s = (int)g[e]; d = (int)g[E + e];
        } else {
            const int* g = (const int*)graph;
            s = g[e]; d = g[E + e];
        }
    } else {
        s = d = e - E;   // self loop
    }

    float4 as4 = *(const float4*)&g_asrc[s * 4];
    float4 ad4 = *(const float4*)&g_adst[d * 4];
    float a0 = as4.x + ad4.x, a1 = as4.y + ad4.y, a2 = as4.z + ad4.z, a3 = as4.w + ad4.w;
    a0 = (a0 > 0.f) ? a0 : 0.2f * a0;
    a1 = (a1 > 0.f) ? a1 : 0.2f * a1;
    a2 = (a2 > 0.f) ? a2 : 0.2f * a2;
    a3 = (a3 > 0.f) ? a3 : 0.2f * a3;
    float4 ex4 = make_float4(__expf(a0), __expf(a1), __expf(a2), __expf(a3));

    int pos = atomicAdd(&g_off[d], 1);
    g_msrc[pos] = s;
    g_mex[pos]  = ex4;
}

// ---------------- scatter2: warp/node, Σex·y and Σex, divide at end ---------
__global__ void __launch_bounds__(256) k_scatter2(float* __restrict__ out, int N) {
    int tid = blockIdx.x * blockDim.x + threadIdx.x;
    int g = tid >> 5;
    int lane = tid & 31;
    if (g >= N) return;
    int half = lane >> 4;
    int sub  = lane & 15;
    int base = g_base[g];
    int n = g_cnt[g];

    float4 acc = make_float4(0.f, 0.f, 0.f, 0.f);
    float4 ds  = make_float4(0.f, 0.f, 0.f, 0.f);

    if (n > 0) {
        int j = half;
        int jc = (j < n) ? j : (n - 1);
        int    src_n = __ldg(&g_msrc[base + jc]);
        float4 ex_n  = __ldg(&g_mex[base + jc]);
        bool   v_n   = (j < n);

        for (int i = 0; i < n; i += 2) {
            int    src = src_n;
            float4 c   = ex_n;
            bool   v   = v_n;
            int nj = i + 2 + half;
            int njc = (nj < n) ? nj : (n - 1);
            src_n = __ldg(&g_msrc[base + njc]);
            ex_n  = __ldg(&g_mex[base + njc]);
            v_n   = (nj < n);

            if (!v) { c.x = 0.f; c.y = 0.f; c.z = 0.f; c.w = 0.f; }
            ds.x += c.x; ds.y += c.y; ds.z += c.z; ds.w += c.w;

            const uint4* yp = (const uint4*)&g_y2[(size_t)src * 256];
            uint4 ua = __ldg(&yp[2 * sub]);
            uint4 ub = __ldg(&yp[2 * sub + 1]);

            float2 h0a = __half22float2(*(__half2*)&ua.x);
            float2 h0b = __half22float2(*(__half2*)&ua.y);
            float2 h1a = __half22float2(*(__half2*)&ua.z);
            float2 h1b = __half22float2(*(__half2*)&ua.w);
            float2 h2a = __half22float2(*(__half2*)&ub.x);
            float2 h2b = __half22float2(*(__half2*)&ub.y);
            float2 h3a = __half22float2(*(__half2*)&ub.z);
            float2 h3b = __half22float2(*(__half2*)&ub.w);

            acc.x += fmaf(c.w, h3a.x, fmaf(c.z, h2a.x, fmaf(c.y, h1a.x, c.x * h0a.x)));
            acc.y += fmaf(c.w, h3a.y, fmaf(c.z, h2a.y, fmaf(c.y, h1a.y, c.x * h0a.y)));
            acc.z += fmaf(c.w, h3b.x, fmaf(c.z, h2b.x, fmaf(c.y, h1b.x, c.x * h0b.x)));
            acc.w += fmaf(c.w, h3b.y, fmaf(c.z, h2b.y, fmaf(c.y, h1b.y, c.x * h0b.y)));
        }
    }

    acc.x += __shfl_xor_sync(0xffffffffu, acc.x, 16);
    acc.y += __shfl_xor_sync(0xffffffffu, acc.y, 16);
    acc.z += __shfl_xor_sync(0xffffffffu, acc.z, 16);
    acc.w += __shfl_xor_sync(0xffffffffu, acc.w, 16);
    ds.x  += __shfl_xor_sync(0xffffffffu, ds.x, 16);
    ds.y  += __shfl_xor_sync(0xffffffffu, ds.y, 16);
    ds.z  += __shfl_xor_sync(0xffffffffu, ds.z, 16);
    ds.w  += __shfl_xor_sync(0xffffffffu, ds.w, 16);

    if (half == 0) {
        float4 rdn;
        rdn.x = __fdividef(1.f, ds.x + 1e-16f);
        rdn.y = __fdividef(1.f, ds.y + 1e-16f);
        rdn.z = __fdividef(1.f, ds.z + 1e-16f);
        rdn.w = __fdividef(1.f, ds.w + 1e-16f);
        // heads interleave as: acc component q corresponds to dim 4*sub+q,
        // with per-head coefs already folded in — ds division is per-head-sum;
        // since acc already mixed heads with ex weights, divide is per-head:
        // acc = sum_h ex_h*y_h summed with same ds_h for all heads? No:
        // each fma used c.{x,y,z,w} = ex of head 0..3 and h{0..3} features, so
        // out_dim d gets sum_h ex_h*y[h][d'] — but each head needs its OWN 1/ds.
        // The packing maps acc components to FIXED dims with all 4 heads mixed,
        // so we must divide per head BEFORE mixing. Instead we divided nothing
        // yet: recompute properly below using per-head accumulators is wrong.
        // => This path requires per-head accs; handled by construction: each
        // acc component is sum over heads of ex_h*y_h[dim]; division must be
        // applied per head. We therefore scale inside the loop instead.
        // (See k_scatter2b below — this branch is unreachable.)
        float4 b4 = *(const float4*)&g_b2[4 * sub];
        acc.x = fmaf(acc.x, 1.f, b4.x);
        acc.y = fmaf(acc.y, 1.f, b4.y);
        acc.z = fmaf(acc.z, 1.f, b4.z);
        acc.w = fmaf(acc.w, 1.f, b4.w);
        (void)rdn;
        *(float4*)&out[(size_t)g * 64 + 4 * sub] = acc;
    }
}

// NOTE: the end-division requires per-head separation which the packed
// accumulate destroys. Correct version: compute ds in a quick pre-pass over
// the group's ex (meta is L2-hot, 16B per edge), then scale in-loop.
__global__ void __launch_bounds__(256) k_scatter2b(float* __restrict__ out, int N) {
    int tid = blockIdx.x * blockDim.x + threadIdx.x;
    int g = tid >> 5;
    int lane = tid & 31;
    if (g >= N) return;
    int half = lane >> 4;
    int sub  = lane & 15;
    int base = g_base[g];
    int n = g_cnt[g];

    // pre-pass: denom per head — lanes cooperatively sum ex (strided by 32/4=8)
    float4 ds = make_float4(0.f, 0.f, 0.f, 0.f);
    for (int i = lane; i < n; i += 32) {
        float4 ex = __ldg(&g_mex[base + i]);
        ds.x += ex.x; ds.y += ex.y; ds.z += ex.z; ds.w += ex.w;
    }
    #pragma unroll
    for (int o = 16; o; o >>= 1) {
        ds.x += __shfl_xor_sync(0xffffffffu, ds.x, o);
        ds.y += __shfl_xor_sync(0xffffffffu, ds.y, o);
        ds.z += __shfl_xor_sync(0xffffffffu, ds.z, o);
        ds.w += __shfl_xor_sync(0xffffffffu, ds.w, o);
    }
    float4 rdn;
    rdn.x = __fdividef(1.f, ds.x + 1e-16f);
    rdn.y = __fdividef(1.f, ds.y + 1e-16f);
    rdn.z = __fdividef(1.f, ds.z + 1e-16f);
    rdn.w = __fdividef(1.f, ds.w + 1e-16f);

    float4 acc = make_float4(0.f, 0.f, 0.f, 0.f);

    if (n > 0) {
        int j = half;
        int jc = (j < n) ? j : (n - 1);
        int    src_n = __ldg(&g_msrc[base + jc]);
        float4 ex_n  = __ldg(&g_mex[base + jc]);
        bool   v_n   = (j < n);

        for (int i = 0; i < n; i += 2) {
            int    src = src_n;
            float4 ex  = ex_n;
            bool   v   = v_n;
            int nj = i + 2 + half;
            int njc = (nj < n) ? nj : (n - 1);
            src_n = __ldg(&g_msrc[base + njc]);
            ex_n  = __ldg(&g_mex[base + njc]);
            v_n   = (nj < n);

            float4 c;
            c.x = v ? ex.x * rdn.x : 0.f;
            c.y = v ? ex.y * rdn.y : 0.f;
            c.z = v ? ex.z * rdn.z : 0.f;
            c.w = v ? ex.w * rdn.w : 0.f;

            const uint4* yp = (const uint4*)&g_y2[(size_t)src * 256];
            uint4 ua = __ldg(&yp[2 * sub]);
            uint4 ub = __ldg(&yp[2 * sub + 1]);

            float2 h0a = __half22float2(*(__half2*)&ua.x);
            float2 h0b = __half22float2(*(__half2*)&ua.y);
            float2 h1a = __half22float2(*(__half2*)&ua.z);
            float2 h1b = __half22float2(*(__half2*)&ua.w);
            float2 h2a = __half22float2(*(__half2*)&ub.x);
            float2 h2b = __half22float2(*(__half2*)&ub.y);
            float2 h3a = __half22float2(*(__half2*)&ub.z);
            float2 h3b = __half22float2(*(__half2*)&ub.w);

            acc.x += fmaf(c.w, h3a.x, fmaf(c.z, h2a.x, fmaf(c.y, h1a.x, c.x * h0a.x)));
            acc.y += fmaf(c.w, h3a.y, fmaf(c.z, h2a.y, fmaf(c.y, h1a.y, c.x * h0a.y)));
            acc.z += fmaf(c.w, h3b.x, fmaf(c.z, h2b.x, fmaf(c.y, h1b.x, c.x * h0b.x)));
            acc.w += fmaf(c.w, h3b.y, fmaf(c.z, h2b.y, fmaf(c.y, h1b.y, c.x * h0b.y)));
        }
    }

    acc.x += __shfl_xor_sync(0xffffffffu, acc.x, 16);
    acc.y += __shfl_xor_sync(0xffffffffu, acc.y, 16);
    acc.z += __shfl_xor_sync(0xffffffffu, acc.z, 16);
    acc.w += __shfl_xor_sync(0xffffffffu, acc.w, 16);

    if (half == 0) {
        float4 b4 = *(const float4*)&g_b2[4 * sub];
        acc.x += b4.x; acc.y += b4.y; acc.z += b4.z; acc.w += b4.w;
        *(float4*)&out[(size_t)g * 64 + 4 * sub] = acc;
    }
}

// ---------------- launch ----------------
extern "C" void kernel_launch(void* const* d_in, const int* in_sizes, int n_in,
                              void* d_out, int out_size) {
    const float* emb   = (const float*)d_in[0];
    const void*  graph = d_in[1];
    const float* W     = (const float*)d_in[2];
    const float* asr   = (const float*)d_in[3];
    const float* adt   = (const float*)d_in[4];
    const float* bias  = (const float*)d_in[5];
    const float* dw    = (const float*)d_in[6];
    const float* db    = (const float*)d_in[7];
    float* out = (float*)d_out;

    int N  = in_sizes[0] / 64;
    int E  = in_sizes[1] / 2;
    int ET = E + N;
    int nb = (N + 1023) / 1024;
    int P  = (N + 63) / 64;
    int HB = (ET + 255) / 256;

    k_prep<<<266 + (N + 63) / 64, 64>>>(W, dw, asr, adt, bias, db,
                                        (const int*)graph, N);
    k_phase1h<<<P + HB, 256>>>(emb, graph, N, E, ET, P);
    k_scanA<<<nb, 1024>>>(N);
    k_scanB<<<1, 64>>>(nb);
    k_scanC<<<nb, 1024>>>(N);
    k_edge2<<<(ET + 255) / 256, 256>>>(graph, E, ET);
    k_scatter2b<<<((size_t)N * 32 + 255) / 256, 256>>>(out, N);
}